// round 11
// baseline (speedup 1.0000x reference)
#include <cuda_runtime.h>
#include <cstdint>

#define D_MODEL     2048
#define NUM_EXPERTS 64
#define TOP_K       4
#define TM          32               // tokens per CTA
#define KC          32               // K chunk
#define NCHUNK      (D_MODEL / KC)   // 64
#define N_TOKENS    16384
#define NBLK        (N_TOKENS / TM)  // 512

#define AWW         36               // A row stride words (32 + 4 pad; 144B, 16B-aligned)
#define A_STAGE_B   (TM * AWW * 4)   // 4608 B
#define BWU         36               // B k-row stride in ULL (32 pairs + pad; 288B)
#define B_STAGE_B   (KC * BWU * 8)   // 9216 B
#define B_OFF       (2 * A_STAGE_B)  // 9216
#define SBUF_BYTES  (B_OFF + 2 * B_STAGE_B)   // 27648

__device__ float g_expert_partial[NBLK * NUM_EXPERTS];
__device__ int   g_done;             // zero-init; reset by last CTA each run

__device__ __forceinline__ uint32_t smem_to_u32(const void* p) {
    uint32_t a;
    asm("{ .reg .u64 t; cvta.to.shared.u64 t, %1; cvt.u32.u64 %0, t; }" : "=r"(a) : "l"(p));
    return a;
}
#define CP_ASYNC16(dst_u32, src_ptr) \
    asm volatile("cp.async.cg.shared.global [%0], [%1], 16;" :: "r"(dst_u32), "l"(src_ptr))
#define CP_COMMIT() asm volatile("cp.async.commit_group;" ::: "memory")
#define CP_WAIT1()  asm volatile("cp.async.wait_group 1;" ::: "memory")
#define CP_WAIT0()  asm volatile("cp.async.wait_group 0;" ::: "memory")

__device__ __forceinline__ void fma2(unsigned long long& d, unsigned long long a, unsigned long long b) {
    asm("fma.rn.f32x2 %0, %1, %2, %0;" : "+l"(d) : "l"(a), "l"(b));
}
__device__ __forceinline__ unsigned long long dup2(float x) {
    unsigned long long r;
    uint32_t xb = __float_as_uint(x);
    asm("mov.b64 %0, {%1, %1};" : "=l"(r) : "r"(xb));
    return r;
}
__device__ __forceinline__ void unpack2(unsigned long long v, float& lo, float& hi) {
    uint32_t l, h;
    asm("mov.b64 {%0, %1}, %2;" : "=r"(l), "=r"(h) : "l"(v));
    lo = __uint_as_float(l); hi = __uint_as_float(h);
}

__global__ void __launch_bounds__(128, 6) router_kernel(
    const float* __restrict__ u, const float* __restrict__ E,
    const float* __restrict__ bias,
    float* __restrict__ out_idx, float* __restrict__ out_val,
    float* __restrict__ out_scores, float* __restrict__ out_aux)
{
    __shared__ __align__(16) char sbuf[SBUF_BYTES];
    __shared__ float biasS[NUM_EXPERTS];
    __shared__ float redA[2][NUM_EXPERTS];
    __shared__ float sq[NUM_EXPERTS];
    __shared__ int   lastFlag;

    const uint32_t sb = smem_to_u32(sbuf);
    const int tid = threadIdx.x, lid = tid & 31, wid = tid >> 5;
    const int tg = lid & 7;              // token slot: tokens tg + 8i
    const int pg = lid >> 3;             // 0..3
    const int p0 = wid * 8 + pg * 2;     // pairs p0, p0+1 (experts 2p0..2p0+3)
    const int tokBase = blockIdx.x * TM;

    if (tid < NUM_EXPERTS) biasS[tid] = bias[tid];

    auto issue = [&](int c) {
        const int st = c & 1;
        const int k0 = c * KC;
        const uint32_t ab = sb + st * A_STAGE_B;
        const uint32_t bb = sb + B_OFF + st * B_STAGE_B;
        // A: 32 rows x 8 x 16B units = 256 units, 2/thread
#pragma unroll
        for (int i = 0; i < 2; i++) {
            int unit = tid + 128 * i;
            int row = unit >> 3, off = unit & 7;
            CP_ASYNC16(ab + (uint32_t)(row * 144 + off * 16),
                       u + (size_t)(tokBase + row) * D_MODEL + k0 + off * 4);
        }
        // B: raw E rows k0..k0+31: 32 rows x 16 units = 512 units, 4/thread
#pragma unroll
        for (int i = 0; i < 4; i++) {
            int unit = tid + 128 * i;
            int kr = unit >> 4, off = unit & 15;
            CP_ASYNC16(bb + (uint32_t)(kr * 288 + off * 16),
                       E + (size_t)(k0 + kr) * NUM_EXPERTS + off * 4);
        }
        CP_COMMIT();
    };

    unsigned long long acc[4][2];
#pragma unroll
    for (int i = 0; i < 4; i++) { acc[i][0] = 0ull; acc[i][1] = 0ull; }

    issue(0);
    issue(1);

    for (int c = 0; c < NCHUNK; c++) {
        if (c < NCHUNK - 1) CP_WAIT1(); else CP_WAIT0();
        __syncthreads();

        const int st = c & 1;
        const float* as = (const float*)(sbuf + st * A_STAGE_B);
        const unsigned long long* bs = (const unsigned long long*)(sbuf + B_OFF + st * B_STAGE_B);

#pragma unroll 8
        for (int k = 0; k < KC; k++) {
            unsigned long long av[4], bv[2];
#pragma unroll
            for (int i = 0; i < 4; i++)
                av[i] = dup2(as[(tg + 8 * i) * AWW + k]);
            bv[0] = bs[k * BWU + p0];
            bv[1] = bs[k * BWU + p0 + 1];
#pragma unroll
            for (int i = 0; i < 4; i++) {
                fma2(acc[i][0], av[i], bv[0]);
                fma2(acc[i][1], av[i], bv[1]);
            }
        }
        __syncthreads();
        if (c + 2 < NCHUNK) issue(c + 2);
    }

    // ---- epilogue: acc -> L[32][65] (overlays sbuf; 8320 B) ----
    float* L = (float*)sbuf;
#pragma unroll
    for (int i = 0; i < 4; i++) {
        const int t = tg + 8 * i;
#pragma unroll
        for (int j = 0; j < 2; j++) {
            const int e0 = 2 * (p0 + j);
            float lo, hi;
            unpack2(acc[i][j], lo, hi);
            L[t * 65 + e0]     = lo;
            L[t * 65 + e0 + 1] = hi;
        }
    }
    __syncthreads();

    if (tid < TM) {
        const int t = tid;
        float p[64];
        float mx = -1e30f;
#pragma unroll
        for (int e = 0; e < 64; e++) { p[e] = L[t * 65 + e] + biasS[e]; mx = fmaxf(mx, p[e]); }
        float s = 0.f;
#pragma unroll
        for (int e = 0; e < 64; e++) { p[e] = expf(p[e] - mx); s += p[e]; }
        const float inv = 1.f / s;
#pragma unroll
        for (int e = 0; e < 64; e++) p[e] *= inv;

        const int gtok = tokBase + t;
        unsigned long long chosen = 0ull;
#pragma unroll
        for (int r = 0; r < TOP_K; r++) {
            float bv = -1.f; int bi = 0;
#pragma unroll
            for (int e = 0; e < 64; e++) {
                bool skip = (chosen >> e) & 1ull;
                if (!skip && p[e] > bv) { bv = p[e]; bi = e; }  // strict >: lowest idx ties
            }
            chosen |= 1ull << bi;
            out_idx[(size_t)gtok * TOP_K + r] = (float)bi;
            out_val[(size_t)gtok * TOP_K + r] = bv;
        }
#pragma unroll
        for (int e = 0; e < 64; e++) L[t * 65 + e] = p[e];
    }
    __syncthreads();

    // coalesced scores writeback: 2048 floats, 16/thread
#pragma unroll
    for (int i = 0; i < 16; i++) {
        int idx = tid + i * 128;
        int t = idx >> 6, e = idx & 63;
        out_scores[(size_t)(tokBase + t) * NUM_EXPERTS + e] = L[t * 65 + e];
    }
    // deterministic per-block expert sums
    if (tid < NUM_EXPERTS) {
        float s = 0.f;
#pragma unroll
        for (int t = 0; t < TM; t++) s += L[t * 65 + tid];
        g_expert_partial[(size_t)blockIdx.x * NUM_EXPERTS + tid] = s;
    }

    // ---- elected-last-CTA aux reduction (deterministic fixed-order sums) ----
    __threadfence();
    if (tid == 0) lastFlag = (atomicAdd(&g_done, 1) == NBLK - 1) ? 1 : 0;
    __syncthreads();
    if (lastFlag) {
        const int e = tid & 63, h = tid >> 6;      // 2 halves x 64 experts
        float s = 0.f;
        const int b0 = h * (NBLK / 2);
#pragma unroll 8
        for (int b = 0; b < NBLK / 2; b++)
            s += g_expert_partial[(size_t)(b0 + b) * NUM_EXPERTS + e];
        redA[h][e] = s;
        __syncthreads();
        if (tid < 64) {
            float m = (redA[0][tid] + redA[1][tid]) * (1.f / (float)N_TOKENS);
            sq[tid] = m * m;
        }
        __syncthreads();
        if (tid == 0) {
            float a = 0.f;
#pragma unroll
            for (int k = 0; k < 64; k++) a += sq[k];
            out_aux[0] = a * (float)NUM_EXPERTS;
            g_done = 0;                            // reset for next replay
        }
    }
}

extern "C" void kernel_launch(void* const* d_in, const int* in_sizes, int n_in,
                              void* d_out, int out_size)
{
    const float* u    = (const float*)d_in[0];
    const float* E    = (const float*)d_in[1];
    const float* bias = (const float*)d_in[2];

    float* out        = (float*)d_out;
    float* out_idx    = out;
    float* out_val    = out_idx + (size_t)N_TOKENS * TOP_K;
    float* out_scores = out_val + (size_t)N_TOKENS * TOP_K;
    float* out_aux    = out_scores + (size_t)N_TOKENS * NUM_EXPERTS;

    router_kernel<<<NBLK, 128>>>(u, E, bias, out_idx, out_val, out_scores, out_aux);
}